// round 4
// baseline (speedup 1.0000x reference)
#include <cuda_runtime.h>
#include <cuda_bf16.h>

// Fast Walsh-Hadamard transform, 16384 rows x 1024 fp32.
// y[row] = FWHT(x[row]) / 32, emitted as interleaved (real, 0) pairs.
//
// First stage folded into the load:
//   FWHT_1024(x) = [ FWHT_512(x_lo + x_hi) ; FWHT_512(x_lo - x_hi) ]
// Two independent warps per row (same block -> loads merge in L1/MSHR),
// each runs a warp-local 512-FWHT with 16 values/thread:
//   stride 512        -> folded into load (sum/diff half)
//   stride 1          -> register butterfly (b pair)
//   strides 2..32     -> 5 shfl.xor stages
//   strides 64..256   -> register butterflies over j
// No shared memory, no barriers, ~38 regs -> high occupancy.

#define DIMN 1024
#define HALFN 512
#define RPB  4            // rows per block (2 warps/row) -> 256 threads

__device__ __forceinline__ void bf(float &x, float &y) {
    float s = x + y;
    y = x - y;
    x = s;
}

__global__ void __launch_bounds__(256, 6)
fwht_kernel(const float2* __restrict__ xin, float4* __restrict__ yout, int nrows)
{
    const int l    = threadIdx.x & 31;
    const int w    = threadIdx.x >> 5;
    const int row  = blockIdx.x * RPB + (w >> 1);
    const int half = w & 1;                 // 0: sum half, 1: diff half
    if (row >= nrows) return;

    // Thread owns elements e = 2l + b + 64j (b in {0,1}, j in 0..7) of the
    // 512-point derived vector; loads both input halves at those positions.
    const float2* lo = xin + (size_t)row * (DIMN / 2) + l;
    const float2* hi = lo + (HALFN / 2);

    // ---- 16 independent coalesced LDG.64, front-batched ----
    float2 u[8], v[8];
    #pragma unroll
    for (int j = 0; j < 8; j++) u[j] = lo[32 * j];
    #pragma unroll
    for (int j = 0; j < 8; j++) v[j] = hi[32 * j];

    // ---- stride 512 folded: a = u +/- v (exact via fmaf with +/-1) ----
    const float sgn = half ? -1.0f : 1.0f;
    float a[8], b[8];
    #pragma unroll
    for (int j = 0; j < 8; j++) {
        a[j] = fmaf(sgn, v[j].x, u[j].x);   // element 2l   + 64j
        b[j] = fmaf(sgn, v[j].y, u[j].y);   // element 2l+1 + 64j
    }

    // ---- stride 1 (register, b-pair) ----
    #pragma unroll
    for (int j = 0; j < 8; j++) bf(a[j], b[j]);

    // ---- strides 2,4,8,16,32 via shfl.xor on lane bits ----
    #pragma unroll
    for (int d = 1; d <= 16; d <<= 1) {
        const bool up = (l & d) != 0;
        #pragma unroll
        for (int j = 0; j < 8; j++) {
            float oa = __shfl_xor_sync(0xffffffffu, a[j], d);
            float ob = __shfl_xor_sync(0xffffffffu, b[j], d);
            a[j] = up ? (oa - a[j]) : (a[j] + oa);
            b[j] = up ? (ob - b[j]) : (b[j] + ob);
        }
    }

    // ---- strides 64,128,256: butterflies over j bits ----
    #pragma unroll
    for (int s = 1; s <= 4; s <<= 1) {
        #pragma unroll
        for (int j = 0; j < 8; j++) {
            if ((j & s) == 0) {
                bf(a[j], a[j + s]);
                bf(b[j], b[j + s]);
            }
        }
    }

    // ---- scaled, interleaved (real, 0) stores; 8 coalesced STG.128 ----
    // Global output element e_g = 512*half + 2l + 64j -> float4 index e_g/2.
    const float sc = 0.03125f;   // 1/sqrt(1024)
    float4* out = yout + (size_t)row * (2 * DIMN / 4) + 256 * half + l;
    #pragma unroll
    for (int j = 0; j < 8; j++) {
        __stcs(out + 32 * j, make_float4(a[j] * sc, 0.0f, b[j] * sc, 0.0f));
    }
}

extern "C" void kernel_launch(void* const* d_in, const int* in_sizes, int n_in,
                              void* d_out, int out_size)
{
    const float* x = (const float*)d_in[0];   // [B, S, 1024] fp32
    // d_in[1] is H; unused — the transform is computed directly.
    float* out = (float*)d_out;               // [B, S, 1024, 2] fp32

    const int nrows = in_sizes[0] / DIMN;     // 16384
    const int grid  = (nrows + RPB - 1) / RPB;

    fwht_kernel<<<grid, 256>>>((const float2*)x, (float4*)out, nrows);
}